// round 6
// baseline (speedup 1.0000x reference)
#include <cuda_runtime.h>
#include <cstdint>

// ---- problem constants ----
#define B_ 4
#define N_ 4
#define D_ 41
#define FH_ 16
#define FW_ 44
#define C_ 64
#define NX_ 240
#define NY_ 240
#define NPTS_ (B_*N_*D_*FH_*FW_)      // 461824 = 1804*256
#define NSPAT_ (NY_*NX_)              // 57600
#define SCRATCH_ELEMS_ (B_*NSPAT_*C_) // 14745600

// channel-last accumulation scratch [b][y][x][c]
// Zero-initialized at module load; transpose_kernel re-zeroes it every call,
// so it is zero at entry to every kernel_launch invocation.
__device__ __align__(16) float g_scratch[SCRATCH_ELEMS_];
// per-(b,n): invPostRot[9], combine[9], trans[3], post_trans[3]
__device__ float g_mats[B_*N_][24];
// frustum u coordinates (numpy linspace bits, precomputed once)
__device__ float g_utab[FW_];

// non-FMA 3-dot, left-assoc ascending (XLA decomposed-dot semantics)
__device__ __forceinline__ float dot3(float c0, float c1, float c2,
                                      float p0, float p1, float p2) {
    return __fadd_rn(__fadd_rn(__fmul_rn(c0, p0), __fmul_rn(c1, p1)),
                     __fmul_rn(c2, p2));
}

// f32 3x3 inverse via LU (partial pivoting) + triangular solves,
// back-substitution uses reciprocal-of-diagonal MULTIPLY (cuBLAS trsm style).
__device__ __forceinline__ void inv3x3_cublas_f32(const float a[9], float o[9]) {
    float LU[9];
    #pragma unroll
    for (int k = 0; k < 9; k++) LU[k] = a[k];
    int perm[3] = {0, 1, 2};
    #pragma unroll
    for (int k = 0; k < 2; k++) {
        int p = k;
        float best = fabsf(LU[k*3 + k]);
        #pragma unroll
        for (int i = k + 1; i < 3; i++) {
            float v = fabsf(LU[i*3 + k]);
            if (v > best) { best = v; p = i; }
        }
        if (p != k) {
            #pragma unroll
            for (int j = 0; j < 3; j++) {
                float t = LU[k*3 + j]; LU[k*3 + j] = LU[p*3 + j]; LU[p*3 + j] = t;
            }
            int t = perm[k]; perm[k] = perm[p]; perm[p] = t;
        }
        float rkk = __fdiv_rn(1.0f, LU[k*3 + k]);
        #pragma unroll
        for (int i = k + 1; i < 3; i++) {
            float l = __fmul_rn(LU[i*3 + k], rkk);
            LU[i*3 + k] = l;
            #pragma unroll
            for (int j = k + 1; j < 3; j++)
                LU[i*3 + j] = __fadd_rn(LU[i*3 + j], -__fmul_rn(l, LU[k*3 + j]));
        }
    }
    float r0 = __fdiv_rn(1.0f, LU[0]);
    float r1 = __fdiv_rn(1.0f, LU[4]);
    float r2 = __fdiv_rn(1.0f, LU[8]);
    #pragma unroll
    for (int c = 0; c < 3; c++) {
        float y0 = (perm[0] == c) ? 1.0f : 0.0f;
        float y1 = (perm[1] == c) ? 1.0f : 0.0f;
        float y2 = (perm[2] == c) ? 1.0f : 0.0f;
        y1 = __fadd_rn(y1, -__fmul_rn(LU[3], y0));
        y2 = __fadd_rn(y2, -__fmul_rn(LU[6], y0));
        y2 = __fadd_rn(y2, -__fmul_rn(LU[7], y1));
        float x2 = __fmul_rn(y2, r2);
        float x1 = __fmul_rn(__fadd_rn(y1, -__fmul_rn(LU[5], x2)), r1);
        float x0 = __fmul_rn(__fadd_rn(__fadd_rn(y0, -__fmul_rn(LU[1], x1)),
                                       -__fmul_rn(LU[2], x2)), r0);
        o[0*3 + c] = x0; o[1*3 + c] = x1; o[2*3 + c] = x2;
    }
}

__global__ void setup_kernel(const float* __restrict__ rots,
                             const float* __restrict__ trans,
                             const float* __restrict__ intrins,
                             const float* __restrict__ post_rots,
                             const float* __restrict__ post_trans) {
    int i = threadIdx.x;
    // frustum u table: numpy linspace semantics (f64 w*step, endpoint override)
    if (i < FW_)
        g_utab[i] = (i == FW_-1) ? 703.0f : (float)((double)i * (703.0 / 43.0));
    if (i >= B_*N_) return;
    float A[9], iK[9], ipr[9], R[9];
    #pragma unroll
    for (int k = 0; k < 9; k++) A[k] = intrins[i*9 + k];
    inv3x3_cublas_f32(A, iK);
    #pragma unroll
    for (int k = 0; k < 9; k++) A[k] = post_rots[i*9 + k];
    inv3x3_cublas_f32(A, ipr);
    #pragma unroll
    for (int k = 0; k < 9; k++) R[k] = rots[i*9 + k];

    float* M = g_mats[i];
    #pragma unroll
    for (int k = 0; k < 9; k++) M[k] = ipr[k];
    #pragma unroll
    for (int r = 0; r < 3; r++)
        #pragma unroll
        for (int c = 0; c < 3; c++)
            M[9 + r*3 + c] = dot3(R[r*3+0], R[r*3+1], R[r*3+2],
                                  iK[c], iK[3+c], iK[6+c]);
    M[18] = trans[i*3+0];      M[19] = trans[i*3+1];      M[20] = trans[i*3+2];
    M[21] = post_trans[i*3+0]; M[22] = post_trans[i*3+1]; M[23] = post_trans[i*3+2];
}

// Two-phase splat: phase 1 = one thread per point -> voxel lin index in smem;
// phase 2 = 4 threads per point move 16 float4 chunks (coalesced 64B groups).
__global__ void __launch_bounds__(256) splat_kernel(const float* __restrict__ x) {
    __shared__ int s_lin[256];
    int tid = threadIdx.x;
    int p = blockIdx.x * 256 + tid;

    // ---- phase 1: geometry (identical arithmetic to the passing R4 kernel) ----
    {
        int w = p % FW_;
        int t = p / FW_;
        int h = t % FH_;  t /= FH_;
        int d = t % D_;   t /= D_;
        int bn = t;                 // b*N + n
        int b  = bn >> 2;           // N_ == 4
        const float* M = g_mats[bn];

        float u   = g_utab[w];
        float v   = (float)(h * 17);            // 255/15 == 17 exact
        float dep = 4.0f + (float)d;

        float p0 = __fadd_rn(u,   -M[21]);
        float p1 = __fadd_rn(v,   -M[22]);
        float p2 = __fadd_rn(dep, -M[23]);
        float a0 = dot3(M[0], M[1], M[2], p0, p1, p2);
        float a1 = dot3(M[3], M[4], M[5], p0, p1, p2);
        float a2 = dot3(M[6], M[7], M[8], p0, p1, p2);
        float X = __fmul_rn(a0, a2);
        float Y = __fmul_rn(a1, a2);
        float Z = a2;
        float qx = __fadd_rn(dot3(M[ 9], M[10], M[11], X, Y, Z), M[18]);
        float qy = __fadd_rn(dot3(M[12], M[13], M[14], X, Y, Z), M[19]);
        float qz = __fadd_rn(dot3(M[15], M[16], M[17], X, Y, Z), M[20]);

        int vx = (int)__fdiv_rn(__fadd_rn(qx, 48.0f), 0.4f);
        int vy = (int)__fdiv_rn(__fadd_rn(qy, 48.0f), 0.4f);
        int vz = (int)__fdiv_rn(__fadd_rn(qz, 10.0f), 20.0f);
        bool kept = (vx >= 0) & (vx < NX_) & (vy >= 0) & (vy < NY_) & (vz == 0);
        s_lin[tid] = kept ? (b * NSPAT_ + vy * NX_ + vx) : -1;
    }
    __syncthreads();

    // ---- phase 2: feature scatter, 4 threads per point ----
    int q = tid & 3;
    int sub = tid >> 2;           // 0..63
    #pragma unroll
    for (int j = 0; j < 4; j++) {
        int ptl = j * 64 + sub;   // local point 0..255
        int lin = s_lin[ptl];
        if (lin < 0) continue;
        const float4* src = reinterpret_cast<const float4*>(
            x + ((size_t)(blockIdx.x * 256 + ptl)) * C_);
        float* dst = g_scratch + (size_t)lin * C_;
        #pragma unroll
        for (int k = 0; k < 4; k++) {
            int chunk = q + 4*k;  // 4 lanes -> contiguous 64B
            float4 f = __ldg(src + chunk);
            asm volatile("red.global.add.v4.f32 [%0], {%1, %2, %3, %4};"
                         :: "l"(dst + 4*chunk), "f"(f.x), "f"(f.y), "f"(f.z), "f"(f.w)
                         : "memory");
        }
    }
}

// [b][y][x][c] -> [b][c][y][x]; 64 spatial x 64 channel tile, float4 both sides.
// Also re-zeroes scratch (read-then-clear, same thread & address) for next call.
__global__ void __launch_bounds__(256) transpose_kernel(float* __restrict__ out) {
    __shared__ float tile[64][65];
    int b  = blockIdx.y;
    int s0 = blockIdx.x * 64;
    float* sc = g_scratch + (size_t)b * NSPAT_ * C_;
    int t = threadIdx.x;
    int row  = t >> 4;     // 0..15
    int quad = t & 15;     // 0..15
    const float4 z4 = make_float4(0.f, 0.f, 0.f, 0.f);
    #pragma unroll
    for (int i = 0; i < 4; i++) {
        int r = row + i*16;
        float4* gp = reinterpret_cast<float4*>(sc + (size_t)(s0 + r) * C_) + quad;
        float4 v = *gp;
        *gp = z4;          // re-zero scratch for the next invocation
        tile[r][quad*4+0] = v.x; tile[r][quad*4+1] = v.y;
        tile[r][quad*4+2] = v.z; tile[r][quad*4+3] = v.w;
    }
    __syncthreads();
    float* ob = out + (size_t)b * C_ * NSPAT_;
    #pragma unroll
    for (int i = 0; i < 4; i++) {
        int lin = t + i*256;      // 0..1023
        int c  = lin >> 4;        // 0..63
        int sq = lin & 15;        // 0..15
        float4 v;
        v.x = tile[sq*4+0][c];
        v.y = tile[sq*4+1][c];
        v.z = tile[sq*4+2][c];
        v.w = tile[sq*4+3][c];
        *reinterpret_cast<float4*>(ob + (size_t)c * NSPAT_ + s0 + sq*4) = v;
    }
}

extern "C" void kernel_launch(void* const* d_in, const int* in_sizes, int n_in,
                              void* d_out, int out_size) {
    const float* x          = (const float*)d_in[0];
    const float* rots       = (const float*)d_in[1];
    const float* trans      = (const float*)d_in[2];
    const float* intrins    = (const float*)d_in[3];
    const float* post_rots  = (const float*)d_in[4];
    const float* post_trans = (const float*)d_in[5];
    float* out = (float*)d_out;

    setup_kernel<<<1, 64>>>(rots, trans, intrins, post_rots, post_trans);
    splat_kernel<<<NPTS_/256, 256>>>(x);
    transpose_kernel<<<dim3(NSPAT_/64, B_), 256>>>(out);
}

// round 7
// speedup vs baseline: 1.6381x; 1.6381x over previous
#include <cuda_runtime.h>
#include <cstdint>

// ---- problem constants ----
#define B_ 4
#define N_ 4
#define D_ 41
#define FH_ 16
#define FW_ 44
#define C_ 64
#define NX_ 240
#define NY_ 240
#define NPTS_ (B_*N_*D_*FH_*FW_)      // 461824 = 1804*256
#define NSPAT_ (NY_*NX_)              // 57600
#define SCRATCH_ELEMS_ (B_*NSPAT_*C_) // 14745600

// channel-last accumulation scratch [b][y][x][c]
__device__ __align__(16) float g_scratch[SCRATCH_ELEMS_];
// per-(b,n): invPostRot[9], combine[9], trans[3], post_trans[3]
__device__ float g_mats[B_*N_][24];
// frustum u coordinates (numpy linspace bits, precomputed once per call)
__device__ float g_utab[FW_];

// non-FMA 3-dot, left-assoc ascending (XLA decomposed-dot semantics)
__device__ __forceinline__ float dot3(float c0, float c1, float c2,
                                      float p0, float p1, float p2) {
    return __fadd_rn(__fadd_rn(__fmul_rn(c0, p0), __fmul_rn(c1, p1)),
                     __fmul_rn(c2, p2));
}

// f32 3x3 inverse via LU (partial pivoting) + triangular solves,
// back-substitution uses reciprocal-of-diagonal MULTIPLY (cuBLAS trsm style).
__device__ __forceinline__ void inv3x3_cublas_f32(const float a[9], float o[9]) {
    float LU[9];
    #pragma unroll
    for (int k = 0; k < 9; k++) LU[k] = a[k];
    int perm[3] = {0, 1, 2};
    #pragma unroll
    for (int k = 0; k < 2; k++) {
        int p = k;
        float best = fabsf(LU[k*3 + k]);
        #pragma unroll
        for (int i = k + 1; i < 3; i++) {
            float v = fabsf(LU[i*3 + k]);
            if (v > best) { best = v; p = i; }
        }
        if (p != k) {
            #pragma unroll
            for (int j = 0; j < 3; j++) {
                float t = LU[k*3 + j]; LU[k*3 + j] = LU[p*3 + j]; LU[p*3 + j] = t;
            }
            int t = perm[k]; perm[k] = perm[p]; perm[p] = t;
        }
        float rkk = __fdiv_rn(1.0f, LU[k*3 + k]);
        #pragma unroll
        for (int i = k + 1; i < 3; i++) {
            float l = __fmul_rn(LU[i*3 + k], rkk);
            LU[i*3 + k] = l;
            #pragma unroll
            for (int j = k + 1; j < 3; j++)
                LU[i*3 + j] = __fadd_rn(LU[i*3 + j], -__fmul_rn(l, LU[k*3 + j]));
        }
    }
    float r0 = __fdiv_rn(1.0f, LU[0]);
    float r1 = __fdiv_rn(1.0f, LU[4]);
    float r2 = __fdiv_rn(1.0f, LU[8]);
    #pragma unroll
    for (int c = 0; c < 3; c++) {
        float y0 = (perm[0] == c) ? 1.0f : 0.0f;
        float y1 = (perm[1] == c) ? 1.0f : 0.0f;
        float y2 = (perm[2] == c) ? 1.0f : 0.0f;
        y1 = __fadd_rn(y1, -__fmul_rn(LU[3], y0));
        y2 = __fadd_rn(y2, -__fmul_rn(LU[6], y0));
        y2 = __fadd_rn(y2, -__fmul_rn(LU[7], y1));
        float x2 = __fmul_rn(y2, r2);
        float x1 = __fmul_rn(__fadd_rn(y1, -__fmul_rn(LU[5], x2)), r1);
        float x0 = __fmul_rn(__fadd_rn(__fadd_rn(y0, -__fmul_rn(LU[1], x1)),
                                       -__fmul_rn(LU[2], x2)), r0);
        o[0*3 + c] = x0; o[1*3 + c] = x1; o[2*3 + c] = x2;
    }
}

__global__ void setup_kernel(const float* __restrict__ rots,
                             const float* __restrict__ trans,
                             const float* __restrict__ intrins,
                             const float* __restrict__ post_rots,
                             const float* __restrict__ post_trans) {
    int i = threadIdx.x;
    // frustum u table: numpy linspace semantics (f64 w*step, endpoint override)
    if (i < FW_)
        g_utab[i] = (i == FW_-1) ? 703.0f : (float)((double)i * (703.0 / 43.0));
    if (i >= B_*N_) return;
    float A[9], iK[9], ipr[9], R[9];
    #pragma unroll
    for (int k = 0; k < 9; k++) A[k] = intrins[i*9 + k];
    inv3x3_cublas_f32(A, iK);
    #pragma unroll
    for (int k = 0; k < 9; k++) A[k] = post_rots[i*9 + k];
    inv3x3_cublas_f32(A, ipr);
    #pragma unroll
    for (int k = 0; k < 9; k++) R[k] = rots[i*9 + k];

    float* M = g_mats[i];
    #pragma unroll
    for (int k = 0; k < 9; k++) M[k] = ipr[k];
    #pragma unroll
    for (int r = 0; r < 3; r++)
        #pragma unroll
        for (int c = 0; c < 3; c++)
            M[9 + r*3 + c] = dot3(R[r*3+0], R[r*3+1], R[r*3+2],
                                  iK[c], iK[3+c], iK[6+c]);
    M[18] = trans[i*3+0];      M[19] = trans[i*3+1];      M[20] = trans[i*3+2];
    M[21] = post_trans[i*3+0]; M[22] = post_trans[i*3+1]; M[23] = post_trans[i*3+2];
}

// Zero the scratch right before splat: also acts as an L2 warm/install pass so
// the splat's REDs hit dirty L2 lines instead of fetching from DRAM.
__global__ void zero_kernel() {
    int idx = blockIdx.x * blockDim.x + threadIdx.x;
    if (idx < SCRATCH_ELEMS_/4) {
        reinterpret_cast<float4*>(g_scratch)[idx] = make_float4(0.f, 0.f, 0.f, 0.f);
    }
}

// Two-phase splat: phase 1 = one thread per point -> voxel lin index in smem;
// phase 2 = 4 threads per point move 16 float4 chunks (coalesced 64B groups).
__global__ void __launch_bounds__(256) splat_kernel(const float* __restrict__ x) {
    __shared__ int s_lin[256];
    int tid = threadIdx.x;
    int p = blockIdx.x * 256 + tid;

    // ---- phase 1: geometry (bit-identical to the passing kernels) ----
    {
        int w = p % FW_;
        int t = p / FW_;
        int h = t % FH_;  t /= FH_;
        int d = t % D_;   t /= D_;
        int bn = t;                 // b*N + n
        int b  = bn >> 2;           // N_ == 4
        const float* M = g_mats[bn];

        float u   = g_utab[w];
        float v   = (float)(h * 17);            // 255/15 == 17 exact
        float dep = 4.0f + (float)d;

        float p0 = __fadd_rn(u,   -M[21]);
        float p1 = __fadd_rn(v,   -M[22]);
        float p2 = __fadd_rn(dep, -M[23]);
        float a0 = dot3(M[0], M[1], M[2], p0, p1, p2);
        float a1 = dot3(M[3], M[4], M[5], p0, p1, p2);
        float a2 = dot3(M[6], M[7], M[8], p0, p1, p2);
        float X = __fmul_rn(a0, a2);
        float Y = __fmul_rn(a1, a2);
        float Z = a2;
        float qx = __fadd_rn(dot3(M[ 9], M[10], M[11], X, Y, Z), M[18]);
        float qy = __fadd_rn(dot3(M[12], M[13], M[14], X, Y, Z), M[19]);
        float qz = __fadd_rn(dot3(M[15], M[16], M[17], X, Y, Z), M[20]);

        int vx = (int)__fdiv_rn(__fadd_rn(qx, 48.0f), 0.4f);
        int vy = (int)__fdiv_rn(__fadd_rn(qy, 48.0f), 0.4f);
        int vz = (int)__fdiv_rn(__fadd_rn(qz, 10.0f), 20.0f);
        bool kept = (vx >= 0) & (vx < NX_) & (vy >= 0) & (vy < NY_) & (vz == 0);
        s_lin[tid] = kept ? (b * NSPAT_ + vy * NX_ + vx) : -1;
    }
    __syncthreads();

    // ---- phase 2: feature scatter, 4 threads per point ----
    int q = tid & 3;
    int sub = tid >> 2;           // 0..63
    #pragma unroll
    for (int j = 0; j < 4; j++) {
        int ptl = j * 64 + sub;   // local point 0..255
        int lin = s_lin[ptl];
        if (lin < 0) continue;
        const float4* src = reinterpret_cast<const float4*>(
            x + ((size_t)(blockIdx.x * 256 + ptl)) * C_);
        float* dst = g_scratch + (size_t)lin * C_;
        #pragma unroll
        for (int k = 0; k < 4; k++) {
            int chunk = q + 4*k;  // 4 lanes -> contiguous 64B
            float4 f = __ldg(src + chunk);
            asm volatile("red.global.add.v4.f32 [%0], {%1, %2, %3, %4};"
                         :: "l"(dst + 4*chunk), "f"(f.x), "f"(f.y), "f"(f.z), "f"(f.w)
                         : "memory");
        }
    }
}

// [b][y][x][c] -> [b][c][y][x]; 64 spatial x 64 channel tile, float4 both sides.
__global__ void __launch_bounds__(256) transpose_kernel(float* __restrict__ out) {
    __shared__ float tile[64][65];
    int b  = blockIdx.y;
    int s0 = blockIdx.x * 64;
    const float* sc = g_scratch + (size_t)b * NSPAT_ * C_;
    int t = threadIdx.x;
    int row  = t >> 4;     // 0..15
    int quad = t & 15;     // 0..15
    #pragma unroll
    for (int i = 0; i < 4; i++) {
        int r = row + i*16;
        float4 v = *(reinterpret_cast<const float4*>(sc + (size_t)(s0 + r) * C_) + quad);
        tile[r][quad*4+0] = v.x; tile[r][quad*4+1] = v.y;
        tile[r][quad*4+2] = v.z; tile[r][quad*4+3] = v.w;
    }
    __syncthreads();
    float* ob = out + (size_t)b * C_ * NSPAT_;
    #pragma unroll
    for (int i = 0; i < 4; i++) {
        int lin = t + i*256;      // 0..1023
        int c  = lin >> 4;        // 0..63
        int sq = lin & 15;        // 0..15
        float4 v;
        v.x = tile[sq*4+0][c];
        v.y = tile[sq*4+1][c];
        v.z = tile[sq*4+2][c];
        v.w = tile[sq*4+3][c];
        *reinterpret_cast<float4*>(ob + (size_t)c * NSPAT_ + s0 + sq*4) = v;
    }
}

extern "C" void kernel_launch(void* const* d_in, const int* in_sizes, int n_in,
                              void* d_out, int out_size) {
    const float* x          = (const float*)d_in[0];
    const float* rots       = (const float*)d_in[1];
    const float* trans      = (const float*)d_in[2];
    const float* intrins    = (const float*)d_in[3];
    const float* post_rots  = (const float*)d_in[4];
    const float* post_trans = (const float*)d_in[5];
    float* out = (float*)d_out;

    setup_kernel<<<1, 64>>>(rots, trans, intrins, post_rots, post_trans);
    zero_kernel<<<(SCRATCH_ELEMS_/4 + 255)/256, 256>>>();
    splat_kernel<<<NPTS_/256, 256>>>(x);
    transpose_kernel<<<dim3(NSPAT_/64, B_), 256>>>(out);
}